// round 10
// baseline (speedup 1.0000x reference)
#include <cuda_runtime.h>
#include <cuda_bf16.h>
#include <cstdint>

// ---------------------------------------------------------------------------
// Problem constants
// ---------------------------------------------------------------------------
#define BB   64
#define CIN  64
#define COUT 128
#define HH   1855
#define KK   6
#define GH   4
#define NCTA ((HH + GH - 1) / GH)   // 464

// ---------------------------------------------------------------------------
// Device global scratch (SW128 pre-swizzled so linear bulk copies land
// bank-conflict-free in smem):
//   g_X: [h][ hi 8192B | lo 8192B ]   row = b (64 rows x 128B), unit^=(b&7)
//   g_W: [j][ hi 16384B | lo 16384B ] row = o (128 rows x 128B), unit^=(o&7)
// ---------------------------------------------------------------------------
__device__ __nv_bfloat16 g_X[(size_t)HH * 8192];   // ~30.4 MB
__device__ __nv_bfloat16 g_W[7 * 16384];
__device__ __nv_bfloat16 g_zero[8192];             // 16 KB zeros

#define W_TILE 16384                       // per precision
#define X_TILE 8192                        // per precision
#define STAGE  (2 * W_TILE + GH * 2 * X_TILE)   // 32768 + 65536 = 98304
#define DSMEM  (2 * STAGE)                 // 196608

// ---------------------------------------------------------------------------
// PTX helpers (plain sm_90-class PTX; no 'a'-gated features)
// ---------------------------------------------------------------------------
__device__ __forceinline__ uint32_t smem_u32(const void* p) {
    uint32_t a;
    asm("{ .reg .u64 t; cvta.to.shared.u64 t, %1; cvt.u32.u64 %0, t; }"
        : "=r"(a) : "l"(p));
    return a;
}

#define MBAR_INIT(mbar, cnt) \
    asm volatile("mbarrier.init.shared.b64 [%0], %1;" \
                 :: "r"(mbar), "r"((uint32_t)(cnt)) : "memory")
#define MBAR_EXPECT_TX(mbar, bytes) \
    asm volatile("mbarrier.arrive.expect_tx.shared.b64 _, [%0], %1;" \
                 :: "r"(mbar), "r"((uint32_t)(bytes)) : "memory")

__device__ __forceinline__ void mbar_wait(uint32_t mbar, uint32_t parity) {
    asm volatile(
        "{\n\t.reg .pred P;\n\t"
        "W_%=:\n\t"
        "mbarrier.try_wait.parity.acquire.cta.shared::cta.b64 P, [%0], %1, 0x989680;\n\t"
        "@P bra.uni D_%=;\n\t"
        "bra.uni W_%=;\n\t"
        "D_%=:\n\t}"
        :: "r"(mbar), "r"(parity) : "memory");
}

__device__ __forceinline__ void bulk_g2s(uint32_t dst, const void* src,
                                         uint32_t bytes, uint32_t mbar) {
    asm volatile(
        "cp.async.bulk.shared::cluster.global.mbarrier::complete_tx::bytes "
        "[%0], [%1], %2, [%3];"
        :: "r"(dst), "l"(src), "r"(bytes), "r"(mbar) : "memory");
}

__device__ __forceinline__ void ldsm4(uint32_t* r, uint32_t addr) {
    asm volatile("ldmatrix.sync.aligned.m8n8.x4.shared.b16 {%0,%1,%2,%3}, [%4];"
                 : "=r"(r[0]), "=r"(r[1]), "=r"(r[2]), "=r"(r[3]) : "r"(addr));
}

__device__ __forceinline__ void mma16816(float* c, const uint32_t* a,
                                         const uint32_t* b) {
    asm volatile(
        "mma.sync.aligned.m16n8k16.row.col.f32.bf16.bf16.f32 "
        "{%0,%1,%2,%3}, {%4,%5,%6,%7}, {%8,%9}, {%0,%1,%2,%3};"
        : "+f"(c[0]), "+f"(c[1]), "+f"(c[2]), "+f"(c[3])
        : "r"(a[0]), "r"(a[1]), "r"(a[2]), "r"(a[3]), "r"(b[0]), "r"(b[1]));
}

__device__ __forceinline__ void split_bf16(float v, unsigned short& hi,
                                           unsigned short& lo) {
    __nv_bfloat16 bh = __float2bfloat16_rn(v);
    __nv_bfloat16 bl = __float2bfloat16_rn(v - __bfloat162float(bh));
    hi = __bfloat16_as_ushort(bh);
    lo = __bfloat16_as_ushort(bl);
}

// ---------------------------------------------------------------------------
// Kernel 1: transpose + hi/lo split + SW128 pre-swizzle of x.
// x[b][c][h] -> g_X[h] slab [b-row][c-col].  grid = (64 b, 58 h-tiles), 256 thr
// ---------------------------------------------------------------------------
__global__ void k_prep(const float* __restrict__ x) {
    __shared__ float s[64][33];
    const int b   = blockIdx.x;
    const int h0  = blockIdx.y * 32;
    const int tid = threadIdx.x;

    for (int e = tid; e < 64 * 32; e += 256) {
        int c = e >> 5, hh = e & 31;
        int h = h0 + hh;
        s[c][hh] = (h < HH) ? x[((size_t)(b * CIN + c)) * HH + h] : 0.f;
    }
    __syncthreads();

    // 512 items: [prec(2)][hh(32)][oct(8)], each a uint4 (8 bf16)
    for (int e = tid; e < 512; e += 256) {
        int prec = e >> 8, idx = e & 255;
        int hh = idx >> 3, oct = idx & 7;
        int h = h0 + hh;
        if (h >= HH) continue;
        unsigned int r[4];
        #pragma unroll
        for (int p = 0; p < 4; p++) {
            unsigned short h0b, l0b, h1b, l1b;
            split_bf16(s[oct * 8 + 2 * p + 0][hh], h0b, l0b);
            split_bf16(s[oct * 8 + 2 * p + 1][hh], h1b, l1b);
            unsigned short u0 = prec ? l0b : h0b;
            unsigned short u1 = prec ? l1b : h1b;
            r[p] = (unsigned)u0 | ((unsigned)u1 << 16);
        }
        uint32_t off = b * 128 + oct * 16;
        uint32_t sw  = off ^ ((off >> 3) & 0x70);    // unit ^= (b & 7)
        char* dst = (char*)g_X + (size_t)h * 16384 + prec * 8192 + sw;
        *(uint4*)dst = make_uint4(r[0], r[1], r[2], r[3]);
    }
}

// ---------------------------------------------------------------------------
// Kernel 2: pack + split + swizzle weights -> g_W[j][hi|lo]
// ---------------------------------------------------------------------------
__global__ void k_packW(const float* __restrict__ wc, const float* __restrict__ wn) {
    int i = blockIdx.x * 256 + threadIdx.x;      // 7*128*64 = 57344
    if (i < 7 * COUT * CIN) {
        int j = i >> 13;
        int o = (i >> 6) & 127;
        int c = i & 63;
        float w = (j == 0) ? wc[o * CIN + c] : wn[(o * CIN + c) * KK + (j - 1)];
        unsigned short uh, ul;
        split_bf16(w, uh, ul);
        uint32_t off = o * 128 + c * 2;
        uint32_t sw  = off ^ ((off >> 3) & 0x70);    // unit ^= (o & 7)
        char* base = (char*)g_W + (size_t)j * 32768;
        *(unsigned short*)(base + sw)          = uh;
        *(unsigned short*)(base + W_TILE + sw) = ul;
    }
}

__global__ void k_zero() {
    int i = blockIdx.x * 1024 + threadIdx.x;
    if (i < 8192) g_zero[i] = __float2bfloat16(0.f);
}

// ---------------------------------------------------------------------------
// Kernel 3: HMMA conv.  CTA = 4 hexagons, 512 threads = 16 warps.
// Warp map: wh = wid & 3 (hexagon), wb = (wid>>2)&1, wo = wid >> 3.
// Per h:  D[o=128, b=64] = sum_j W_j[o, 64c] * X_{n(h,j)}[b, 64c]^T
// 3-term split bf16: Ah*Bh + Ah*Bl + Al*Bh, fp32 accum.
// Double-buffered cp.async.bulk pipeline (5 DMA ops/stage + mbarrier),
// SW128-swizzled smem (swizzle pre-applied in global layout).
// ---------------------------------------------------------------------------
__global__ __launch_bounds__(512, 1)
void k_conv(const int* __restrict__ nbr, const float* __restrict__ bias,
            float* __restrict__ out) {
    extern __shared__ char dsm[];
    const uint32_t base = smem_u32(dsm);

    __shared__ int   s_sidx[GH][7];
    __shared__ float s_inv[GH];
    __shared__ float s_bias[COUT];
    __shared__ __align__(8) unsigned long long s_bar[2];

    const int tid  = threadIdx.x;
    const int lane = tid & 31;
    const int wid  = tid >> 5;
    const int wh = wid & 3;
    const int wb = (wid >> 2) & 1;
    const int wo = wid >> 3;
    const int h0 = blockIdx.x * GH;
    const int gcnt = min(GH, HH - h0);

    if (tid < GH * 7) {
        int hh = tid / 7, j = tid % 7;
        int v = -1;
        int h = h0 + hh;
        if (h < HH) v = (j == 0) ? h : nbr[h * KK + (j - 1)];
        s_sidx[hh][j] = v;
    }
    if (tid < COUT) s_bias[tid] = bias[tid];
    if (tid < 2) MBAR_INIT(smem_u32(&s_bar[tid]), 1);
    __syncthreads();
    if (tid < GH) {
        int cnt = 1;
        #pragma unroll
        for (int j = 1; j < 7; j++) cnt += (s_sidx[tid][j] >= 0);
        s_inv[tid] = 1.0f / (float)cnt;
    }
    __syncthreads();

    const uint32_t bar[2] = { smem_u32(&s_bar[0]), smem_u32(&s_bar[1]) };

    // ---- bulk stage issue: 1x W(32KB) + 4x X(16KB) DMA per stage ----
    auto issue = [&](int j, int s) {
        const uint32_t sb = base + s * STAGE;
        MBAR_EXPECT_TX(bar[s], STAGE);
        bulk_g2s(sb, (const char*)g_W + (size_t)j * 32768, 32768, bar[s]);
        #pragma unroll
        for (int hh = 0; hh < GH; hh++) {
            int hv = s_sidx[hh][j];
            const void* src = (hv >= 0)
                ? (const void*)((const char*)g_X + (size_t)hv * 16384)
                : (const void*)g_zero;
            bulk_g2s(sb + 2 * W_TILE + hh * 2 * X_TILE, src, 16384, bar[s]);
        }
    };

    if (tid == 0) { issue(0, 0); issue(1, 1); }

    // ---- fragment addressing (SW128: unit ^= row&7 at 16B granularity) ----
    const uint32_t rowA = (uint32_t)(wo * 64 + (lane & 15)) * 128;
    const uint32_t rowB = (uint32_t)(wb * 32 + (lane & 7) + ((lane >> 4) << 3)) * 128;
    const int swz = lane & 7;              // (rowA&7)==(rowB&7)==lane&7
    const int cA  = (lane >> 4) & 1;
    const int cB  = (lane >> 3) & 1;

    float acc[4][4][4];
    #pragma unroll
    for (int mi = 0; mi < 4; mi++)
        #pragma unroll
        for (int ni = 0; ni < 4; ni++)
            #pragma unroll
            for (int c = 0; c < 4; c++) acc[mi][ni][c] = 0.f;

    for (int j = 0; j < 7; j++) {
        const int s = j & 1;
        mbar_wait(bar[s], (j >> 1) & 1);

        const uint32_t WbH = base + s * STAGE;
        const uint32_t WbL = WbH + W_TILE;
        const uint32_t XbH = WbH + 2 * W_TILE + wh * 2 * X_TILE;
        const uint32_t XbL = XbH + X_TILE;

        #pragma unroll 1
        for (int ks = 0; ks < 4; ks++) {
            const uint32_t uA = (uint32_t)(((ks * 2 + cA) ^ swz) << 4);
            const uint32_t uB = (uint32_t)(((ks * 2 + cB) ^ swz) << 4);
            // phase 1: Ah * Bh
            uint32_t ah[4][4], bh[2][4];
            #pragma unroll
            for (int mi = 0; mi < 4; mi++)
                ldsm4(ah[mi], WbH + rowA + mi * 2048 + uA);
            ldsm4(bh[0], XbH + rowB + uB);
            ldsm4(bh[1], XbH + rowB + 2048 + uB);
            #pragma unroll
            for (int mi = 0; mi < 4; mi++)
                #pragma unroll
                for (int ni = 0; ni < 4; ni++)
                    mma16816(acc[mi][ni], ah[mi], &bh[ni >> 1][(ni & 1) * 2]);
            // phase 2: Ah * Bl   (ah dies after)
            {
                uint32_t bl[2][4];
                ldsm4(bl[0], XbL + rowB + uB);
                ldsm4(bl[1], XbL + rowB + 2048 + uB);
                #pragma unroll
                for (int mi = 0; mi < 4; mi++)
                    #pragma unroll
                    for (int ni = 0; ni < 4; ni++)
                        mma16816(acc[mi][ni], ah[mi], &bl[ni >> 1][(ni & 1) * 2]);
            }
            // phase 3: Al * Bh
            {
                uint32_t al[4][4];
                #pragma unroll
                for (int mi = 0; mi < 4; mi++)
                    ldsm4(al[mi], WbL + rowA + mi * 2048 + uA);
                #pragma unroll
                for (int mi = 0; mi < 4; mi++)
                    #pragma unroll
                    for (int ni = 0; ni < 4; ni++)
                        mma16816(acc[mi][ni], al[mi], &bh[ni >> 1][(ni & 1) * 2]);
            }
        }
        __syncthreads();                  // all reads of buffer s done
        if (j + 2 <= 6 && tid == 0) issue(j + 2, s);
    }

    // ---- epilogue: scale + bias, transpose through smem, h-grouped stores ----
    __syncthreads();
    float* SF = (float*)dsm + (size_t)wh * (64 * 132);   // [b][o], o-stride 132
    const float inv = s_inv[wh];
    #pragma unroll
    for (int mi = 0; mi < 4; mi++)
        #pragma unroll
        for (int ni = 0; ni < 4; ni++)
            #pragma unroll
            for (int c = 0; c < 4; c++) {
                int o = wo * 64 + mi * 16 + (lane >> 2) + ((c & 2) ? 8 : 0);
                int b = wb * 32 + ni * 8 + (lane & 3) * 2 + (c & 1);
                SF[b * 132 + o] = acc[mi][ni][c] * inv + s_bias[o];
            }
    __syncthreads();

    float* S0 = (float*)dsm;
    for (int i = tid; i < BB * COUT; i += 512) {
        int b = i >> 7, o = i & 127;
        size_t addr = ((size_t)(b * COUT + o)) * HH + h0;
        #pragma unroll
        for (int k = 0; k < GH; k++)
            if (k < gcnt) out[addr + k] = S0[(size_t)k * (64 * 132) + b * 132 + o];
    }
}

// ---------------------------------------------------------------------------
extern "C" void kernel_launch(void* const* d_in, const int* in_sizes, int n_in,
                              void* d_out, int out_size) {
    const float* x    = (const float*)d_in[0];
    const int*   nbr  = (const int*)  d_in[1];
    const float* wc   = (const float*)d_in[2];
    const float* wn   = (const float*)d_in[3];
    const float* bias = (const float*)d_in[4];
    float*       out  = (float*)d_out;

    cudaFuncSetAttribute(k_conv, cudaFuncAttributeMaxDynamicSharedMemorySize,
                         DSMEM);

    k_prep <<<dim3(64, (HH + 31) / 32), 256>>>(x);
    k_packW<<<(7 * COUT * CIN + 255) / 256, 256>>>(wc, wn);
    k_zero <<<8, 1024>>>();
    k_conv <<<NCTA, 512, DSMEM>>>(nbr, bias, out);
}

// round 12
// speedup vs baseline: 2.2483x; 2.2483x over previous
#include <cuda_runtime.h>
#include <cuda_fp16.h>
#include <cstdint>

// ---------------------------------------------------------------------------
// Problem constants
// ---------------------------------------------------------------------------
#define BB   64
#define CIN  64
#define COUT 128
#define HH   1855
#define KK   6
#define GH   2
#define NCTA ((HH + GH - 1) / GH)   // 928

// ---------------------------------------------------------------------------
// Device global scratch
//   g_X: [h][b][c] fp16, 4096 elems (8 KB) per h
//   g_W: [j][o][c] fp16, 8192 elems (16 KB) per j   (j = 0 center, 1..6 nbr)
// ---------------------------------------------------------------------------
__device__ __half g_X[(size_t)HH * 4096];   // ~15.2 MB
__device__ __half g_W[7 * 8192];
__device__ __half g_zero[4096];             // 8 KB zeros

// Padded smem rows: 64 fp16 data + 8 pad = 144 B (conflict-free ldmatrix)
#define RS     144
#define W_TILE (128 * RS)                 // 18432 B
#define X_TILE (64 * RS)                  //  9216 B
#define STAGE  (W_TILE + GH * X_TILE)     // 36864 B
#define DSMEM  (2 * STAGE)                // 73728 B  -> 2 CTAs/SM

// ---------------------------------------------------------------------------
// PTX helpers (plain sm_80+ PTX)
// ---------------------------------------------------------------------------
__device__ __forceinline__ uint32_t smem_u32(const void* p) {
    uint32_t a;
    asm("{ .reg .u64 t; cvta.to.shared.u64 t, %1; cvt.u32.u64 %0, t; }"
        : "=r"(a) : "l"(p));
    return a;
}

__device__ __forceinline__ void cp16(uint32_t dst, const void* src) {
    asm volatile("cp.async.cg.shared.global [%0], [%1], 16;"
                 :: "r"(dst), "l"(src) : "memory");
}
__device__ __forceinline__ void cp_commit() {
    asm volatile("cp.async.commit_group;" ::: "memory");
}
__device__ __forceinline__ void cp_wait1() {
    asm volatile("cp.async.wait_group 1;" ::: "memory");
}
__device__ __forceinline__ void cp_wait0() {
    asm volatile("cp.async.wait_group 0;" ::: "memory");
}

__device__ __forceinline__ void ldsm4(uint32_t* r, uint32_t addr) {
    asm volatile("ldmatrix.sync.aligned.m8n8.x4.shared.b16 {%0,%1,%2,%3}, [%4];"
                 : "=r"(r[0]), "=r"(r[1]), "=r"(r[2]), "=r"(r[3]) : "r"(addr));
}

__device__ __forceinline__ void mma16816(float* c, const uint32_t* a,
                                         const uint32_t* b) {
    asm volatile(
        "mma.sync.aligned.m16n8k16.row.col.f32.f16.f16.f32 "
        "{%0,%1,%2,%3}, {%4,%5,%6,%7}, {%8,%9}, {%0,%1,%2,%3};"
        : "+f"(c[0]), "+f"(c[1]), "+f"(c[2]), "+f"(c[3])
        : "r"(a[0]), "r"(a[1]), "r"(a[2]), "r"(a[3]), "r"(b[0]), "r"(b[1]));
}

// ---------------------------------------------------------------------------
// Kernel 1: transpose x[b][c][h] -> g_X[h][b][c] fp16.
// grid = (64 b, 58 h-tiles), 256 threads
// ---------------------------------------------------------------------------
__global__ void k_prep(const float* __restrict__ x) {
    __shared__ float s[64][33];
    const int b   = blockIdx.x;
    const int h0  = blockIdx.y * 32;
    const int tid = threadIdx.x;

    for (int e = tid; e < 64 * 32; e += 256) {
        int c = e >> 5, hh = e & 31;
        int h = h0 + hh;
        s[c][hh] = (h < HH) ? x[((size_t)(b * CIN + c)) * HH + h] : 0.f;
    }
    __syncthreads();

    // 256 items: [hh(32)][oct(8)], each a uint4 (8 fp16)
    for (int e = tid; e < 256; e += 256) {
        int hh = e >> 3, oct = e & 7;
        int h = h0 + hh;
        if (h >= HH) continue;
        unsigned int r[4];
        #pragma unroll
        for (int p = 0; p < 4; p++) {
            __half v0 = __float2half_rn(s[oct * 8 + 2 * p + 0][hh]);
            __half v1 = __float2half_rn(s[oct * 8 + 2 * p + 1][hh]);
            r[p] = (unsigned)__half_as_ushort(v0)
                 | ((unsigned)__half_as_ushort(v1) << 16);
        }
        __half* dst = g_X + (size_t)h * 4096 + b * 64 + oct * 8;
        *(uint4*)dst = make_uint4(r[0], r[1], r[2], r[3]);
    }
}

// ---------------------------------------------------------------------------
// Kernel 2: pack weights -> g_W[j][o][c] fp16
// ---------------------------------------------------------------------------
__global__ void k_packW(const float* __restrict__ wc, const float* __restrict__ wn) {
    int i = blockIdx.x * 256 + threadIdx.x;      // 7*128*64 = 57344
    if (i < 7 * COUT * CIN) {
        int j = i >> 13;
        int o = (i >> 6) & 127;
        int c = i & 63;
        float w = (j == 0) ? wc[o * CIN + c] : wn[(o * CIN + c) * KK + (j - 1)];
        g_W[(size_t)j * 8192 + o * 64 + c] = __float2half_rn(w);
    }
}

__global__ void k_zero() {
    int i = blockIdx.x * 1024 + threadIdx.x;
    if (i < 4096) g_zero[i] = __float2half(0.f);
}

// ---------------------------------------------------------------------------
// Kernel 3: HMMA conv, single-pass fp16.  CTA = 2 hexagons, 256 thr = 8 warps
// (wo 2 x wb 2 x wh 2).  Per h: D[o=128, b=64] = sum_j W_j * X_{n(h,j)}^T.
// Double-buffered cp.async over the 7 K-chunks; 2 CTAs resident per SM.
// ---------------------------------------------------------------------------
__global__ __launch_bounds__(256, 2)
void k_conv(const int* __restrict__ nbr, const float* __restrict__ bias,
            float* __restrict__ out) {
    extern __shared__ char dsm[];
    const uint32_t base = smem_u32(dsm);

    __shared__ int   s_sidx[GH][7];
    __shared__ float s_inv[GH];
    __shared__ float s_bias[COUT];

    const int tid  = threadIdx.x;
    const int lane = tid & 31;
    const int wid  = tid >> 5;
    const int wo = wid >> 2;          // o 64-half
    const int wb = (wid >> 1) & 1;    // b 32-half
    const int wh = wid & 1;           // hexagon
    const int h0 = blockIdx.x * GH;

    if (tid < GH * 7) {
        int hh = tid / 7, j = tid % 7;
        int v = -1;
        int h = h0 + hh;
        if (h < HH) v = (j == 0) ? h : nbr[h * KK + (j - 1)];
        s_sidx[hh][j] = v;
    }
    if (tid < COUT) s_bias[tid] = bias[tid];
    __syncthreads();
    if (tid < GH) {
        int cnt = 1;
        #pragma unroll
        for (int j = 1; j < 7; j++) cnt += (s_sidx[tid][j] >= 0);
        s_inv[tid] = 1.0f / (float)cnt;
    }
    __syncthreads();

    // ---- cp.async stage issue: W 1024 + X 1024 chunks of 16 B ----
    auto issue_stage = [&](int j, int s) {
        const uint32_t sb = base + s * STAGE;
        const char* wsrc = (const char*)g_W + (size_t)j * 16384;
        for (int i = tid; i < 1024; i += 256) {
            int row = i >> 3, oct = i & 7;
            cp16(sb + row * RS + oct * 16, wsrc + row * 128 + oct * 16);
        }
        for (int i = tid; i < 1024; i += 256) {
            int h   = i >> 9;
            int row = (i >> 3) & 63;
            int oct = i & 7;
            int hv  = s_sidx[h][j];
            const char* xsrc = (hv >= 0)
                ? (const char*)g_X + (size_t)hv * 8192
                : (const char*)g_zero;
            cp16(sb + W_TILE + h * X_TILE + row * RS + oct * 16,
                 xsrc + row * 128 + oct * 16);
        }
        cp_commit();
    };

    issue_stage(0, 0);
    issue_stage(1, 1);

    // ---- fragment address offsets ----
    const uint32_t aoff = (uint32_t)(wo * 64 + (lane & 15)) * RS + (lane >> 4) * 16;
    const uint32_t boff = (uint32_t)(wb * 32 + (lane & 7) + (lane >> 4) * 8) * RS
                        + ((lane >> 3) & 1) * 16;

    float acc[4][4][4];
    #pragma unroll
    for (int mi = 0; mi < 4; mi++)
        #pragma unroll
        for (int ni = 0; ni < 4; ni++)
            #pragma unroll
            for (int c = 0; c < 4; c++) acc[mi][ni][c] = 0.f;

    for (int j = 0; j < 7; j++) {
        const int s = j & 1;
        if (j == 6) cp_wait0(); else cp_wait1();
        __syncthreads();

        const uint32_t Wb = base + s * STAGE;
        const uint32_t Xb = Wb + W_TILE + wh * X_TILE;

        #pragma unroll
        for (int ks = 0; ks < 4; ks++) {
            const uint32_t kb = ks * 32;
            uint32_t ah[4][4], bh[2][4];
            #pragma unroll
            for (int mi = 0; mi < 4; mi++)
                ldsm4(ah[mi], Wb + aoff + mi * 16 * RS + kb);
            ldsm4(bh[0], Xb + boff + kb);
            ldsm4(bh[1], Xb + boff + 16 * RS + kb);
            #pragma unroll
            for (int mi = 0; mi < 4; mi++)
                #pragma unroll
                for (int ni = 0; ni < 4; ni++)
                    mma16816(acc[mi][ni], ah[mi], &bh[ni >> 1][(ni & 1) * 2]);
        }
        __syncthreads();                  // all reads of buffer s done
        if (j + 2 <= 6) issue_stage(j + 2, s);
    }

    // ---- epilogue: scale + bias, transpose through smem, h-paired stores ----
    __syncthreads();
    float* SF = (float*)dsm + (size_t)wh * (64 * 132);   // [b][o], o-stride 132
    const float inv = s_inv[wh];
    #pragma unroll
    for (int mi = 0; mi < 4; mi++)
        #pragma unroll
        for (int ni = 0; ni < 4; ni++)
            #pragma unroll
            for (int c = 0; c < 4; c++) {
                int o = wo * 64 + mi * 16 + (lane >> 2) + ((c & 2) ? 8 : 0);
                int b = wb * 32 + ni * 8 + (lane & 3) * 2 + (c & 1);
                SF[b * 132 + o] = acc[mi][ni][c] * inv + s_bias[o];
            }
    __syncthreads();

    float* S0 = (float*)dsm;
    const bool has2 = (h0 + 1) < HH;
    for (int i = tid; i < BB * COUT; i += 256) {
        int b = i >> 7, o = i & 127;
        size_t addr = ((size_t)(b * COUT + o)) * HH + h0;
        out[addr] = S0[b * 132 + o];
        if (has2) out[addr + 1] = S0[64 * 132 + b * 132 + o];
    }
}

// ---------------------------------------------------------------------------
extern "C" void kernel_launch(void* const* d_in, const int* in_sizes, int n_in,
                              void* d_out, int out_size) {
    const float* x    = (const float*)d_in[0];
    const int*   nbr  = (const int*)  d_in[1];
    const float* wc   = (const float*)d_in[2];
    const float* wn   = (const float*)d_in[3];
    const float* bias = (const float*)d_in[4];
    float*       out  = (float*)d_out;

    cudaFuncSetAttribute(k_conv, cudaFuncAttributeMaxDynamicSharedMemorySize,
                         DSMEM);

    k_prep <<<dim3(64, (HH + 31) / 32), 256>>>(x);
    k_packW<<<(7 * COUT * CIN + 255) / 256, 256>>>(wc, wn);
    k_zero <<<4, 1024>>>();
    k_conv <<<NCTA, 256, DSMEM>>>(nbr, bias, out);
}